// round 17
// baseline (speedup 1.0000x reference)
#include <cuda_runtime.h>
#include <cuda_bf16.h>
#include <stdint.h>

#define NTOK 4096
#define NEDGE 131072
#define TNUM 8
#define RNUM 16
#define HNUM 8
#define BNUM 21
#define SEEDS 128
#define CAP 96            // per-row edge-list capacity (avg degree = 32, max ~66)

// ---------------------------------------------------------------------------
// Device scratch.
// RULES (hard-won):
//  * fill_kernel must not write device globals nor contain "memory" asm in
//    the hot loop (R5/R9/R15) — kills no-alias/read-only analysis.
//  * tt8 is passed to fill as a const __restrict__ PARAMETER, not accessed
//    as a global symbol, for the same reason.
//  * one dense sequential 16 KB store stream per block (R14).
// ---------------------------------------------------------------------------
__device__ int    g_zero_region[NTOK + 1];   // [0..NTOK) cursors, [NTOK] overcnt
__device__ int    g_elist[NTOK * CAP];       // packed (dst << 4) | rel, per row
__device__ int    g_over[NEDGE];             // packed (src<<16)|(dst<<4)|rel
__device__ uchar4 g_tt8[NTOK / 4];           // token_type packed to bytes

#define g_cursor  g_zero_region
#define g_overcnt g_zero_region[NTOK]

// ---------------------------------------------------------------------------
__device__ __forceinline__ int bucketize(float dt) {
    float s  = (dt > 0.0f) ? 1.0f : ((dt < 0.0f) ? -1.0f : 0.0f);
    float sl = s * log1pf(fabsf(dt) + 1e-6f);
    float c  = fminf(fmaxf(sl, -5.0f), 5.0f);
    float norm = (c + 5.0f) / (10.0f + 1e-9f);
    int idx = (int)floorf(norm * (float)(BNUM - 1));
    idx = idx < 0 ? 0 : idx;
    idx = idx > (BNUM - 1) ? (BNUM - 1) : idx;
    return idx;
}

// ---------------------------------------------------------------------------
// Build kernel (stream-ordered after the memset node):
//  * packs token_type (int32, values 0..7) into bytes -> 4x fewer L1
//    wavefronts for fill's index loads
//  * builds per-row edge lists
// ---------------------------------------------------------------------------
__global__ __launch_bounds__(256) void build_kernel(
    const int* __restrict__ edge_src,
    const int* __restrict__ edge_dst,
    const int* __restrict__ edge_rel,
    const int* __restrict__ token_type)
{
    cudaTriggerProgrammaticLaunchCompletion();   // fill may begin launching
    const int e = blockIdx.x * blockDim.x + threadIdx.x;

    // Pack token_type -> uchar4 (first 1024 threads)
    if (e < NTOK / 4) {
        const int4 t = reinterpret_cast<const int4*>(token_type)[e];
        g_tt8[e] = make_uchar4((unsigned char)t.x, (unsigned char)t.y,
                               (unsigned char)t.z, (unsigned char)t.w);
    }

    if (e >= NEDGE) return;
    const int s = edge_src[e];
    const int d = edge_dst[e];
    const int r = edge_rel[e];
    const int pos = atomicAdd(&g_cursor[s], 1);
    if (pos < CAP) {
        g_elist[s * CAP + pos] = (d << 4) | r;
    } else {
        const int o = atomicAdd(&g_overcnt, 1);
        g_over[o] = (s << 16) | (d << 4) | r;
    }
}

// ---------------------------------------------------------------------------
// Fill kernel (PDL over build): one block per (i, h) row.
// Grid-dependency sync sits BEFORE the hot loop (hot loop consumes tt8);
// fill's launch latency + LUT prologue still hide under build execution.
//   Phase 1:  uchar4 index load -> gathered coalesced float4 stores.
//   Phase 2a: this row's edges via L2-hit atomicAdd into the fresh row.
//   Phase 2b: overflow entries (normally zero).
// ---------------------------------------------------------------------------
__global__ __launch_bounds__(256) void fill_kernel(
    const uchar4* __restrict__ tt8,           // packed token_type (param!)
    const int*   __restrict__ token_type,     // for the val8 LUT init only
    const float* __restrict__ time_vec,
    const float* __restrict__ typepair_bias,  // (T, T, H)
    const float* __restrict__ temp_bias,      // (B, H)
    const float* __restrict__ adj_rel_bias,   // (R, H)
    float*       __restrict__ out)            // (H, N, N)
{
    const int i = blockIdx.x;
    const int h = blockIdx.y;
    const int tid = threadIdx.x;

    __shared__ float val8[TNUM];
    __shared__ float tb[BNUM];
    __shared__ float relb[RNUM];

    if (tid < TNUM) {
        const int tt_i = token_type[i];
        val8[tid] = typepair_bias[(tt_i * TNUM + tid) * HNUM + h];
    }
    if (tid < BNUM) tb[tid]   = temp_bias[tid * HNUM + h];
    if (tid < RNUM) relb[tid] = adj_rel_bias[tid * HNUM + h];
    __syncthreads();

    cudaGridDependencySynchronize();   // tt8 + cursors/lists now visible

    const bool  is_seed = (i < SEEDS);
    const float ti      = time_vec[i];

    float* __restrict__ orow =
        out + ((size_t)h * NTOK + (size_t)i) * (size_t)NTOK;

    // Phase 1: 4096 elements / (256 thr * 4) = 4 float4 stores per thread.
    // Index load is now 4 bytes/thread (1 L1 wavefront/warp vs 4 for int4).
    #pragma unroll
    for (int j0 = tid * 4; j0 < NTOK; j0 += 256 * 4) {
        const uchar4 t4 = tt8[j0 >> 2];
        float4 v;
        v.x = val8[t4.x];
        v.y = val8[t4.y];
        v.z = val8[t4.z];
        v.w = val8[t4.w];
        if (is_seed) {
            const float4 tv = *reinterpret_cast<const float4*>(time_vec + j0);
            v.x += tb[bucketize(tv.x - ti)];
            v.y += tb[bucketize(tv.y - ti)];
            v.z += tb[bucketize(tv.z - ti)];
            v.w += tb[bucketize(tv.w - ti)];
        }
        *reinterpret_cast<float4*>(orow + j0) = v;
    }
    __syncthreads();               // row fully stored before RMW

    // Phase 2a: this row's edges — L2-hit atomics into the fresh row
    const int count = min(g_cursor[i], CAP);
    for (int e = tid; e < count; e += 256) {
        const int p = g_elist[i * CAP + e];
        atomicAdd(orow + (p >> 4), relb[p & 15]);
    }

    // Phase 2b: overflow entries for this row (normally g_overcnt == 0)
    const int on = g_overcnt;
    for (int e = tid; e < on; e += 256) {
        const int p = g_over[e];
        if ((p >> 16) == i)
            atomicAdd(orow + ((p >> 4) & 0xFFF), relb[p & 15]);
    }
}

// ---------------------------------------------------------------------------
// Launch: memset (graph node) -> build -> (PDL) -> fill.
// ---------------------------------------------------------------------------
extern "C" void kernel_launch(void* const* d_in, const int* in_sizes, int n_in,
                              void* d_out, int out_size)
{
    const int*   token_type    = (const int*)  d_in[0];
    const int*   edge_src      = (const int*)  d_in[1];
    const int*   edge_dst      = (const int*)  d_in[2];
    const int*   edge_rel      = (const int*)  d_in[3];
    const float* time_vec      = (const float*)d_in[4];
    const float* adj_rel_bias  = (const float*)d_in[n_in - 3];
    const float* typepair_bias = (const float*)d_in[n_in - 2];
    const float* temp_bias     = (const float*)d_in[n_in - 1];
    float* out = (float*)d_out;

    // Zero cursors + overcnt via a graph memset node
    void* zr = nullptr;
    cudaGetSymbolAddress(&zr, g_zero_region);
    cudaMemsetAsync(zr, 0, (NTOK + 1) * sizeof(int), 0);

    // Packed token_type address, passed to fill as a restrict parameter
    void* tt8p = nullptr;
    cudaGetSymbolAddress(&tt8p, g_tt8);

    // build: stream-ordered after the memset
    build_kernel<<<(NEDGE + 255) / 256, 256>>>(edge_src, edge_dst, edge_rel,
                                               token_type);

    // fill: PDL over build, one block per (row, head)
    cudaLaunchAttribute pdl[1];
    pdl[0].id = cudaLaunchAttributeProgrammaticStreamSerialization;
    pdl[0].val.programmaticStreamSerializationAllowed = 1;

    cudaLaunchConfig_t cfg = {};
    cfg.gridDim  = dim3(NTOK, HNUM);
    cfg.blockDim = dim3(256);
    cfg.attrs    = pdl;
    cfg.numAttrs = 1;
    cfg.stream   = 0;
    cudaLaunchKernelEx(&cfg, fill_kernel, (const uchar4*)tt8p, token_type,
                       time_vec, typepair_bias, temp_bias, adj_rel_bias, out);
}